// round 17
// baseline (speedup 1.0000x reference)
#include <cuda_runtime.h>
#include <cuda_fp16.h>
#include <cstdint>
#include <math.h>

// Problem constants (fixed shapes from setup_inputs)
#define BATCH   4
#define N1      4096
#define N2      16384
#define D1      512
#define D2      256
#define DO      256
#define M1      (BATCH * N1)   // 16384
#define M2      (BATCH * N2)   // 65536
#define K1_BLOCKS (M1 / 128)   // 128
#define K2_BLOCKS (M2 / 128)   // 512
#define NSRC    (BATCH * N1)   // 16384 source rows

// ---------------------------------------------------------------------------
// Device scratch (allocation-free rule: __device__ globals)
// ---------------------------------------------------------------------------
__device__ float g_feats1[M1 * DO];                         // 16 MB
__device__ __align__(16) __half gA1f[M1 * D1];              // 16 MB
__device__ __align__(16) __half gA2f[M2 * D2];              // 32 MB
__device__ __align__(16) __half gW1f[DO * D1];
__device__ __align__(16) __half gW2f[DO * D2];
__device__ float4 g_knnw[M2];                               // weights (w0,w1,w2,-)
__device__ int4   g_knni[M2];                               // global feats1 row idx
__device__ int    g_k1done;                                 // K1 CTA completion count
__device__ __align__(16) __half gKA[M2 * 16];               // target MMA rows (2 MB)
__device__ __align__(16) __half gKB[NSRC * 16];             // source MMA rows (512 KB)

// ---------------------------------------------------------------------------
// Helpers
// ---------------------------------------------------------------------------
__device__ __forceinline__ uint32_t smem_u32(const void* p) {
    uint32_t a;
    asm("{ .reg .u64 t; cvta.to.shared.u64 t, %1; cvt.u32.u64 %0, t; }"
        : "=r"(a) : "l"(p));
    return a;
}

#define SWZ(o) ((o) ^ (((o) >> 3) & 0x70))

#define CP16(dst, src) \
    asm volatile("cp.async.cg.shared.global [%0], [%1], 16;" :: "r"(dst), "l"(src) : "memory")
#define CP_COMMIT() asm volatile("cp.async.commit_group;" ::: "memory")
#define CP_WAIT0()  asm volatile("cp.async.wait_group 0;" ::: "memory")
#define CP_WAIT1()  asm volatile("cp.async.wait_group 1;" ::: "memory")
#define CP_WAIT2()  asm volatile("cp.async.wait_group 2;" ::: "memory")

__device__ __forceinline__ void ldsm4(uint32_t r[4], uint32_t addr) {
    asm volatile("ldmatrix.sync.aligned.m8n8.x4.shared.b16 {%0,%1,%2,%3}, [%4];"
        : "=r"(r[0]), "=r"(r[1]), "=r"(r[2]), "=r"(r[3]) : "r"(addr));
}
__device__ __forceinline__ void mma_f16(float d[4], const uint32_t a[4], const uint32_t b[2]) {
    asm volatile("mma.sync.aligned.m16n8k16.row.col.f32.f16.f16.f32 "
        "{%0,%1,%2,%3}, {%4,%5,%6,%7}, {%8,%9}, {%0,%1,%2,%3};"
        : "+f"(d[0]), "+f"(d[1]), "+f"(d[2]), "+f"(d[3])
        : "r"(a[0]), "r"(a[1]), "r"(a[2]), "r"(a[3]), "r"(b[0]), "r"(b[1]));
}
// MMA with zero C, fresh D
__device__ __forceinline__ void mma_f16_z(float d[4], const uint32_t a[4], const uint32_t b[2]) {
    float z = 0.f;
    asm volatile("mma.sync.aligned.m16n8k16.row.col.f32.f16.f16.f32 "
        "{%0,%1,%2,%3}, {%4,%5,%6,%7}, {%8,%9}, {%10,%10,%10,%10};"
        : "=f"(d[0]), "=f"(d[1]), "=f"(d[2]), "=f"(d[3])
        : "r"(a[0]), "r"(a[1]), "r"(a[2]), "r"(a[3]), "r"(b[0]), "r"(b[1]), "f"(z));
}

// ---------------------------------------------------------------------------
// fp32 -> fp16 converts
// ---------------------------------------------------------------------------
__global__ __launch_bounds__(256)
void cvt_half_kernel(const float* __restrict__ x, __half* __restrict__ y, int n4)
{
    int i = blockIdx.x * blockDim.x + threadIdx.x;
    int stride = gridDim.x * blockDim.x;
    for (; i < n4; i += stride) {
        float4 v = ((const float4*)x)[i];
        ((__half2*)y)[2 * i + 0] = __floats2half2_rn(v.x, v.y);
        ((__half2*)y)[2 * i + 1] = __floats2half2_rn(v.z, v.w);
    }
}

#define CVT1_N4 (M1 * D1 / 4)
#define CVTW1_N4 (DO * D1 / 4)
#define CVTW2_N4 (DO * D2 / 4)

__global__ __launch_bounds__(256)
void cvt_rest_kernel(const float* __restrict__ x1, __half* __restrict__ y1,
                     const float* __restrict__ x2, __half* __restrict__ y2,
                     const float* __restrict__ x3, __half* __restrict__ y3)
{
    int i = blockIdx.x * blockDim.x + threadIdx.x;
    int stride = gridDim.x * blockDim.x;
    int total = CVT1_N4 + CVTW1_N4 + CVTW2_N4;
    for (; i < total; i += stride) {
        const float* x; __half* y; int j;
        if (i < CVT1_N4)                { x = x1; y = y1; j = i; }
        else if (i < CVT1_N4 + CVTW1_N4){ x = x2; y = y2; j = i - CVT1_N4; }
        else                            { x = x3; y = y3; j = i - CVT1_N4 - CVTW1_N4; }
        float4 v = ((const float4*)x)[j];
        ((__half2*)y)[2 * j + 0] = __floats2half2_rn(v.x, v.y);
        ((__half2*)y)[2 * j + 1] = __floats2half2_rn(v.z, v.w);
    }
}

// ---------------------------------------------------------------------------
// KNN prep: build split-fp16 MMA rows (selection keys only; final weights
// are recomputed in exact fp32 from the chosen indices).
// ---------------------------------------------------------------------------
__global__ __launch_bounds__(256)
void knn_prep_kernel(const float* __restrict__ xyz2,
                     const float* __restrict__ xyz1)
{
    int i = blockIdx.x * blockDim.x + threadIdx.x;
    if (i < M2) {
        const float* p = xyz2 + (size_t)i * 3;
        float x = p[0], y = p[1], z = p[2];
        __half hx = __float2half_rn(x), hy = __float2half_rn(y), hz = __float2half_rn(z);
        __half lx = __float2half_rn(x - __half2float(hx));
        __half ly = __float2half_rn(y - __half2float(hy));
        __half lz = __float2half_rn(z - __half2float(hz));
        __align__(16) __half r[16];
        r[0]=hx; r[1]=hy; r[2]=hz; r[3]=lx; r[4]=ly; r[5]=lz;
        r[6]=hx; r[7]=hy; r[8]=hz;
        r[9]=__float2half_rn(1.f); r[10]=__float2half_rn(1.f);
        r[11]=__half(0.f); r[12]=__half(0.f); r[13]=__half(0.f); r[14]=__half(0.f); r[15]=__half(0.f);
        uint4* d = (uint4*)(gKA + (size_t)i * 16);
        d[0] = ((uint4*)r)[0]; d[1] = ((uint4*)r)[1];
    } else if (i < M2 + NSRC) {
        int j = i - M2;
        const float* p = xyz1 + (size_t)j * 3;
        float x = p[0], y = p[1], z = p[2];
        float px = -2.f * x, py = -2.f * y, pz = -2.f * z;
        __half hx = __float2half_rn(px), hy = __float2half_rn(py), hz = __float2half_rn(pz);
        __half lx = __float2half_rn(px - __half2float(hx));
        __half ly = __float2half_rn(py - __half2float(hy));
        __half lz = __float2half_rn(pz - __half2float(hz));
        float sn = fmaf(x, x, fmaf(y, y, z * z));
        __half snh = __float2half_rn(sn);
        __half snl = __float2half_rn(sn - __half2float(snh));
        __align__(16) __half r[16];
        r[0]=hx; r[1]=hy; r[2]=hz; r[3]=hx; r[4]=hy; r[5]=hz;
        r[6]=lx; r[7]=ly; r[8]=lz; r[9]=snh; r[10]=snl;
        r[11]=__half(0.f); r[12]=__half(0.f); r[13]=__half(0.f); r[14]=__half(0.f); r[15]=__half(0.f);
        uint4* d = (uint4*)(gKB + (size_t)j * 16);
        d[0] = ((uint4*)r)[0]; d[1] = ((uint4*)r)[1];
    }
}

// ---------------------------------------------------------------------------
// KNN via tensor cores, pair-screened top-3 insert, exact fp32 re-distance.
// ---------------------------------------------------------------------------
#define KCH   512                 // sources per chunk
#define KROW  48u                 // smem row stride (32B data + 16B pad)
#define KNN_SA (128 * 48)
#define KNN_SB (KCH * 48)
#define KNN_MMA_SMEM (KNN_SA + 2 * KNN_SB + 128)

#define INS3(K0,K1,K2,I0,I1,I2,v,c) \
    if ((v) < K2) { \
        if ((v) < K0)      { K2=K1; I2=I1; K1=K0; I1=I0; K0=(v); I0=(c); } \
        else if ((v) < K1) { K2=K1; I2=I1; K1=(v); I1=(c); } \
        else               { K2=(v); I2=(c); } }

__global__ __launch_bounds__(256)
void knn_mma_kernel(const float* __restrict__ xyz2,
                    const float* __restrict__ xyz1)
{
    extern __shared__ char dsm[];
    const int tid  = threadIdx.x;
    const int wid  = tid >> 5;
    const int lane = tid & 31;
    const int b    = blockIdx.y;
    const int bm   = blockIdx.x * 128;

    if (blockIdx.x == 0 && b == 0 && tid == 0) g_k1done = 0;

    uint32_t base = (smem_u32(dsm) + 127u) & ~127u;
    uint32_t sA = base;
    uint32_t sB = base + KNN_SA;

    const __half* gA = gKA + ((size_t)b * N2 + bm) * 16;
    const __half* gB = gKB + ((size_t)b * N1) * 16;

    auto loadB = [&](int c) {
        uint32_t dst = sB + (uint32_t)(c & 1) * KNN_SB;
        const __half* src = gB + (size_t)c * KCH * 16;
        for (int i = tid; i < 1024; i += 256) {
            int row = i >> 1, h = i & 1;
            CP16(dst + row * KROW + h * 16u, (const char*)(src + row * 16 + h * 8));
        }
        CP_COMMIT();
    };

    // prologue: A rows (128 rows x 2 halves = exactly 1 cp16 per thread)
    {
        int row = tid >> 1, h = tid & 1;
        CP16(sA + row * KROW + h * 16u, (const char*)(gA + row * 16 + h * 8));
    }
    loadB(0);

    float K0l = 3.4e38f, K1l = 3.4e38f, K2l = 3.4e38f;
    float K0h = 3.4e38f, K1h = 3.4e38f, K2h = 3.4e38f;
    int I0l = 0, I1l = 0, I2l = 0, I0h = 0, I1h = 0, I2h = 0;

    const int tr  = lane >> 2, tq = lane & 3;
    const int g   = lane >> 3;
    const int bnrow = (g >> 1) * 8 + (lane & 7);
    const uint32_t bkb = (g & 1) * 16u;

    uint32_t af[4];
    const int NCH = N1 / KCH;   // 8

    for (int c = 0; c < NCH; c++) {
        if (c + 1 < NCH) { loadB(c + 1); CP_WAIT1(); }
        else             { CP_WAIT0(); }
        __syncthreads();
        if (c == 0) {
            ldsm4(af, sA + (uint32_t)(wid * 16 + (lane & 15)) * KROW + (uint32_t)(lane >> 4) * 16u);
        }
        uint32_t sBc = sB + (uint32_t)(c & 1) * KNN_SB;

        for (int blk = 0; blk < 8; blk++) {
            uint32_t bf[8][2];
#pragma unroll
            for (int p = 0; p < 4; p++) {
                uint32_t r[4];
                ldsm4(r, sBc + (uint32_t)(blk * 64 + p * 16 + bnrow) * KROW + bkb);
                bf[2 * p + 0][0] = r[0]; bf[2 * p + 0][1] = r[1];
                bf[2 * p + 1][0] = r[2]; bf[2 * p + 1][1] = r[3];
            }
            float d[8][4];
#pragma unroll
            for (int ni = 0; ni < 8; ni++)
                mma_f16_z(d[ni], af, bf[ni]);

            int colbase = c * KCH + blk * 64 + 2 * tq;
#pragma unroll
            for (int ni = 0; ni < 8; ni++) {
                int cb = colbase + ni * 8;
                float v0 = d[ni][0], v1 = d[ni][1], v2 = d[ni][2], v3 = d[ni][3];
                // pair screening: common path = fmin + setp + not-taken branch
                float mlo = fminf(v0, v1);
                if (mlo < K2l) {
                    INS3(K0l, K1l, K2l, I0l, I1l, I2l, v0, cb);
                    INS3(K0l, K1l, K2l, I0l, I1l, I2l, v1, cb + 1);
                }
                float mhi = fminf(v2, v3);
                if (mhi < K2h) {
                    INS3(K0h, K1h, K2h, I0h, I1h, I2h, v2, cb);
                    INS3(K0h, K1h, K2h, I0h, I1h, I2h, v3, cb + 1);
                }
            }
        }
        if (c + 1 < NCH) __syncthreads();
    }

    // merge top-3 across the 4 quad threads (butterfly: all lanes converge)
#pragma unroll
    for (int off = 1; off <= 2; off <<= 1) {
        float m0 = __shfl_xor_sync(0xFFFFFFFFu, K0l, off);
        float m1 = __shfl_xor_sync(0xFFFFFFFFu, K1l, off);
        float m2 = __shfl_xor_sync(0xFFFFFFFFu, K2l, off);
        int   j0 = __shfl_xor_sync(0xFFFFFFFFu, I0l, off);
        int   j1 = __shfl_xor_sync(0xFFFFFFFFu, I1l, off);
        int   j2 = __shfl_xor_sync(0xFFFFFFFFu, I2l, off);
        INS3(K0l, K1l, K2l, I0l, I1l, I2l, m0, j0);
        INS3(K0l, K1l, K2l, I0l, I1l, I2l, m1, j1);
        INS3(K0l, K1l, K2l, I0l, I1l, I2l, m2, j2);
        m0 = __shfl_xor_sync(0xFFFFFFFFu, K0h, off);
        m1 = __shfl_xor_sync(0xFFFFFFFFu, K1h, off);
        m2 = __shfl_xor_sync(0xFFFFFFFFu, K2h, off);
        j0 = __shfl_xor_sync(0xFFFFFFFFu, I0h, off);
        j1 = __shfl_xor_sync(0xFFFFFFFFu, I1h, off);
        j2 = __shfl_xor_sync(0xFFFFFFFFu, I2h, off);
        INS3(K0h, K1h, K2h, I0h, I1h, I2h, m0, j0);
        INS3(K0h, K1h, K2h, I0h, I1h, I2h, m1, j1);
        INS3(K0h, K1h, K2h, I0h, I1h, I2h, m2, j2);
    }

    if (tq == 0) {
#pragma unroll
        for (int half = 0; half < 2; half++) {
            int r = bm + wid * 16 + tr + half * 8;
            int   ii0 = half ? I0h : I0l, ii1 = half ? I1h : I1l, ii2 = half ? I2h : I2l;
            const float* tp = xyz2 + ((size_t)b * N2 + r) * 3;
            float tx = tp[0], ty = tp[1], tz = tp[2];
            float tt = fmaf(tx, tx, fmaf(ty, ty, tz * tz));
            // exact fp32 distances (reference expansion form) for the winners
            float dd[3];
            int   ids[3] = { ii0, ii1, ii2 };
#pragma unroll
            for (int k = 0; k < 3; k++) {
                const float* sp = xyz1 + ((size_t)b * N1 + ids[k]) * 3;
                float sx = sp[0], sy = sp[1], sz = sp[2];
                float sn = fmaf(sx, sx, fmaf(sy, sy, sz * sz));
                float dot = fmaf(tx, sx, fmaf(ty, sy, tz * sz));
                dd[k] = tt - 2.f * dot + sn;
            }
            float w0 = 1.f / (dd[0] + 1e-8f);
            float w1 = 1.f / (dd[1] + 1e-8f);
            float w2 = 1.f / (dd[2] + 1e-8f);
            float inv = 1.f / (w0 + w1 + w2);
            int gidx = b * N2 + r;
            g_knnw[gidx] = make_float4(w0 * inv, w1 * inv, w2 * inv, 0.f);
            g_knni[gidx] = make_int4(b * N1 + ii0, b * N1 + ii1, b * N1 + ii2, 0);
        }
    }
}

// ---------------------------------------------------------------------------
// Fused dual GEMM + BN + ReLU (+ interp for K2 part).  (unchanged, proven)
// ---------------------------------------------------------------------------
#define STAGE 49152u
#define GEMM_DSMEM (3 * 49152 + 1024)

__device__ __forceinline__ void load_chunk(int tid, int bm, int K,
                                           uint32_t base, int c,
                                           const __half* __restrict__ A,
                                           const __half* __restrict__ B)
{
    uint32_t sb = base + (uint32_t)(c % 3) * STAGE;
    int kc = c << 6;
    for (int i = tid; i < 1024; i += 512) {
        int row = i >> 3, seg = i & 7;
        uint32_t off = SWZ((uint32_t)(row * 128 + seg * 16));
        CP16(sb + off, (const char*)(A + (size_t)(bm + row) * K + kc + seg * 8));
    }
    for (int i = tid; i < 2048; i += 512) {
        int row = i >> 3, seg = i & 7;
        uint32_t off = SWZ((uint32_t)(row * 128 + seg * 16));
        CP16(sb + 16384u + off, (const char*)(B + (size_t)row * K + kc + seg * 8));
    }
    CP_COMMIT();
}

__global__ __launch_bounds__(512, 1)
void gemm_fused_kernel(const __half* __restrict__ A1,
                       const __half* __restrict__ W1h,
                       const __half* __restrict__ A2,
                       const __half* __restrict__ W2h,
                       const float* __restrict__ b1, const float* __restrict__ g1,
                       const float* __restrict__ be1, const float* __restrict__ m1,
                       const float* __restrict__ v1,
                       const float* __restrict__ b2, const float* __restrict__ g2,
                       const float* __restrict__ be2, const float* __restrict__ m2,
                       const float* __restrict__ v2,
                       float* __restrict__ feats1,
                       float* __restrict__ out)
{
    extern __shared__ char dsm[];
    __shared__ float sScale[DO], sShift[DO], sBias[DO];

    const bool isK1 = (blockIdx.x < K1_BLOCKS);
    const __half* A  = isK1 ? A1 : A2;
    const __half* Bw = isK1 ? W1h : W2h;
    const float* bias  = isK1 ? b1 : b2;
    const float* gamma = isK1 ? g1 : g2;
    const float* beta  = isK1 ? be1 : be2;
    const float* mean  = isK1 ? m1 : m2;
    const float* var   = isK1 ? v1 : v2;
    float* C = isK1 ? feats1 : out;
    const int K  = isK1 ? D1 : D2;
    const int bm = (isK1 ? blockIdx.x : (blockIdx.x - K1_BLOCKS)) * 128;
    const int NC = K >> 6;

    const int tid  = threadIdx.x;
    const int wid  = tid >> 5;
    const int lane = tid & 31;
    const int wm   = wid >> 2;
    const int wn   = wid & 3;
    uint32_t base  = (smem_u32(dsm) + 1023u) & ~1023u;

    if (tid < DO) {
        float sc = gamma[tid] * rsqrtf(var[tid] + 1e-5f);
        sScale[tid] = sc;
        sShift[tid] = beta[tid] - mean[tid] * sc;
        sBias[tid]  = bias[tid];
    }

    float acc[2][8][4];
#pragma unroll
    for (int mi = 0; mi < 2; mi++)
#pragma unroll
        for (int ni = 0; ni < 8; ni++)
#pragma unroll
            for (int e = 0; e < 4; e++) acc[mi][ni][e] = 0.f;

    load_chunk(tid, bm, K, base, 0, A, Bw);
    if (NC > 1) load_chunk(tid, bm, K, base, 1, A, Bw);

    const int arow  = wm * 32 + (lane & 15);
    const int acolb = (lane >> 4) * 16;
    const int g     = lane >> 3;
    const int bnrow = (g >> 1) * 8 + (lane & 7);
    const int bkb   = (g & 1) * 16;

    for (int c = 0; c < NC; c++) {
        if (c + 2 < NC) {
            load_chunk(tid, bm, K, base, c + 2, A, Bw);
            CP_WAIT2();
        } else if (c + 1 < NC) {
            CP_WAIT1();
        } else {
            CP_WAIT0();
        }
        __syncthreads();

        uint32_t sb = base + (uint32_t)(c % 3) * STAGE;
        uint32_t sA = sb, sB = sb + 16384u;

#pragma unroll
        for (int kk = 0; kk < 4; kk++) {
            uint32_t af[2][4], bf[8][2];
#pragma unroll
            for (int mi = 0; mi < 2; mi++) {
                uint32_t off = SWZ((uint32_t)((arow + mi * 16) * 128 + kk * 32 + acolb));
                ldsm4(af[mi], sA + off);
            }
#pragma unroll
            for (int p = 0; p < 4; p++) {
                uint32_t r[4];
                uint32_t off = SWZ((uint32_t)((wn * 64 + p * 16 + bnrow) * 128 + kk * 32 + bkb));
                ldsm4(r, sB + off);
                bf[2 * p + 0][0] = r[0]; bf[2 * p + 0][1] = r[1];
                bf[2 * p + 1][0] = r[2]; bf[2 * p + 1][1] = r[3];
            }
#pragma unroll
            for (int mi = 0; mi < 2; mi++)
#pragma unroll
                for (int ni = 0; ni < 8; ni++)
                    mma_f16(acc[mi][ni], af[mi], bf[ni]);
        }
        if (c + 1 < NC) __syncthreads();
    }

    const int tr = lane >> 2, tq = lane & 3;

    if (isK1) {
#pragma unroll
        for (int mi = 0; mi < 2; mi++) {
#pragma unroll
            for (int half = 0; half < 2; half++) {
                int row = bm + wm * 32 + mi * 16 + tr + half * 8;
                float* outRow = C + (size_t)row * DO;
#pragma unroll
                for (int ni = 0; ni < 8; ni++) {
                    int col = wn * 64 + ni * 8 + 2 * tq;
                    int e = half * 2;
                    float2 v;
                    v.x = fmaxf((acc[mi][ni][e + 0] + sBias[col])     * sScale[col]     + sShift[col],     0.f);
                    v.y = fmaxf((acc[mi][ni][e + 1] + sBias[col + 1]) * sScale[col + 1] + sShift[col + 1], 0.f);
                    *(float2*)(outRow + col) = v;
                }
            }
        }
        __threadfence();
        __syncthreads();
        if (tid == 0) atomicAdd(&g_k1done, 1);
    } else {
        if (tid == 0) {
            while (true) {
                int done;
                asm volatile("ld.global.acquire.gpu.b32 %0, [%1];"
                             : "=r"(done) : "l"(&g_k1done));
                if (done == K1_BLOCKS) break;
                __nanosleep(64);
            }
        }
        __syncthreads();
        __threadfence();

#pragma unroll
        for (int mi = 0; mi < 2; mi++) {
#pragma unroll
            for (int half = 0; half < 2; half++) {
                int row = bm + wm * 32 + mi * 16 + tr + half * 8;
                float4 w4  = g_knnw[row];
                int4   id4 = g_knni[row];
                const float* f0 = g_feats1 + (size_t)id4.x * DO;
                const float* f1 = g_feats1 + (size_t)id4.y * DO;
                const float* f2 = g_feats1 + (size_t)id4.z * DO;
                float* outRow = C + (size_t)row * DO;
#pragma unroll
                for (int ni = 0; ni < 8; ni++) {
                    int col = wn * 64 + ni * 8 + 2 * tq;
                    int e = half * 2;
                    float2 v;
                    v.x = fmaxf((acc[mi][ni][e + 0] + sBias[col])     * sScale[col]     + sShift[col],     0.f);
                    v.y = fmaxf((acc[mi][ni][e + 1] + sBias[col + 1]) * sScale[col + 1] + sShift[col + 1], 0.f);
                    float2 e0 = *(const float2*)(f0 + col);
                    float2 e1 = *(const float2*)(f1 + col);
                    float2 e2 = *(const float2*)(f2 + col);
                    v.x += w4.x * e0.x + w4.y * e1.x + w4.z * e2.x;
                    v.y += w4.x * e0.y + w4.y * e1.y + w4.z * e2.y;
                    *(float2*)(outRow + col) = v;
                }
            }
        }
    }
}

// ---------------------------------------------------------------------------
extern "C" void kernel_launch(void* const* d_in, const int* in_sizes, int n_in,
                              void* d_out, int out_size)
{
    const float* xyz1    = (const float*)d_in[0];
    const float* points1 = (const float*)d_in[1];
    const float* xyz2    = (const float*)d_in[2];
    const float* points2 = (const float*)d_in[3];
    const float* W1  = (const float*)d_in[4];
    const float* b1  = (const float*)d_in[5];
    const float* g1  = (const float*)d_in[6];
    const float* be1 = (const float*)d_in[7];
    const float* m1  = (const float*)d_in[8];
    const float* v1  = (const float*)d_in[9];
    const float* W2  = (const float*)d_in[10];
    const float* b2  = (const float*)d_in[11];
    const float* g2  = (const float*)d_in[12];
    const float* be2 = (const float*)d_in[13];
    const float* m2  = (const float*)d_in[14];
    const float* v2  = (const float*)d_in[15];
    float* out = (float*)d_out;

    float* feats1;
    __half *a1f, *a2f, *w1f, *w2f;
    cudaGetSymbolAddress((void**)&feats1, g_feats1);
    cudaGetSymbolAddress((void**)&a1f, gA1f);
    cudaGetSymbolAddress((void**)&a2f, gA2f);
    cudaGetSymbolAddress((void**)&w1f, gW1f);
    cudaGetSymbolAddress((void**)&w2f, gW2f);

    // Launch 1: convert points2 (largest)
    cvt_half_kernel<<<4096, 256>>>(points2, a2f, M2 * D2 / 4);
    // Launch 2: convert points1 + W1 + W2
    cvt_rest_kernel<<<2048, 256>>>(points1, a1f, W1, w1f, W2, w2f);
    // Launch 3: KNN prep (split-fp16 MMA row encodings)
    knn_prep_kernel<<<(M2 + NSRC + 255) / 256, 256>>>(xyz2, xyz1);

    // Launch 4 (ncu capture slot): tensor-core 3-NN
    cudaFuncSetAttribute(knn_mma_kernel,
                         cudaFuncAttributeMaxDynamicSharedMemorySize, KNN_MMA_SMEM);
    {
        dim3 grid(N2 / 128, BATCH);
        knn_mma_kernel<<<grid, 256, KNN_MMA_SMEM>>>(xyz2, xyz1);
    }

    cudaFuncSetAttribute(gemm_fused_kernel,
                         cudaFuncAttributeMaxDynamicSharedMemorySize, GEMM_DSMEM);

    // Launch 5: fused K1 + K2(+interp), 640 CTAs.
    gemm_fused_kernel<<<K1_BLOCKS + K2_BLOCKS, 512, GEMM_DSMEM>>>(
        a1f, w1f, a2f, w2f,
        b1, g1, be1, m1, v1,
        b2, g2, be2, m2, v2,
        feats1, out);
}